// round 4
// baseline (speedup 1.0000x reference)
#include <cuda_runtime.h>

// ScaledDotProductAttention: B=4, W=64, H=64, C=256, M=32, D=32, T=8
// out[b,c,w,h] = sum_m v[b,w,h,c,m] * softmax_m( (q[b,w,h,m,:] . k[b,w,h,:]) / T )
//
// Pure HBM-streaming kernel (594 MB moved once).
// R2: fully coalesced 512B warp loads + shfl reductions.
// R3: 128-thread CTAs, single wave, ~1% imbalance.
// R4: HT=8, smem 10.2 KB, __launch_bounds__(128,10) -> 48 regs, 10 CTAs/SM,
//     40 resident warps (62% occ) for deeper DRAM latency hiding.

#define C_DIM 256
#define M_DIM 32
#define D_DIM 32
#define W_DIM 64
#define H_DIM 64
#define HT 8           // h-tile per CTA

__global__ __launch_bounds__(128, 10)
void sdpa_kernel(const float* __restrict__ q,
                 const float* __restrict__ v,
                 const float* __restrict__ k,
                 float* __restrict__ out)
{
    __shared__ float wts[HT * M_DIM];        // [h_local][m] softmax weights, 1 KB
    __shared__ float res[C_DIM * (HT + 1)];  // [c][h_local], +1 pad, 9.2 KB

    const int hq = blockIdx.x;               // 0..7  (h-tile index)
    const int w  = blockIdx.y;               // 0..63
    const int b  = blockIdx.z;               // 0..3
    const int h0 = hq * HT;

    const int tid  = threadIdx.x;
    const int lane = tid & 31;
    const int wid  = tid >> 5;               // 0..3
    const int sub  = lane & 7;               // position within 8-lane group
    const int grp  = lane >> 3;              // which of 4 groups

    const long slice0 = ((long)(b * W_DIM + w) * H_DIM + h0);

    // ---------- Phase 1: softmax weights; warp wid owns slices wid*2, wid*2+1 ----------
    #pragma unroll
    for (int i = 0; i < 2; ++i) {
        const int  hl = wid * 2 + i;
        const long sl = slice0 + hl;

        const float4 k4 = *(const float4*)(k + sl * D_DIM + sub * 4);

        #pragma unroll
        for (int j = 0; j < 8; ++j) {
            const int m = j * 4 + grp;
            const float4 q4 = __ldcs((const float4*)(q + (sl * M_DIM + m) * D_DIM + sub * 4));
            float p = q4.x * k4.x + q4.y * k4.y + q4.z * k4.z + q4.w * k4.w;
            p += __shfl_xor_sync(0xffffffffu, p, 4);
            p += __shfl_xor_sync(0xffffffffu, p, 2);
            p += __shfl_xor_sync(0xffffffffu, p, 1);
            if (sub == 0) wts[hl * M_DIM + m] = p;   // raw logit
        }
        __syncwarp();

        const float logit = wts[hl * M_DIM + lane] * 0.125f;  // 1/TEMPERATURE
        float mx = logit;
        #pragma unroll
        for (int o = 16; o; o >>= 1) mx = fmaxf(mx, __shfl_xor_sync(0xffffffffu, mx, o));
        const float e = __expf(logit - mx);
        float s = e;
        #pragma unroll
        for (int o = 16; o; o >>= 1) s += __shfl_xor_sync(0xffffffffu, s, o);
        wts[hl * M_DIM + lane] = e / s;
    }
    __syncthreads();

    // ---------- Phase 2: stream v, fully coalesced; warp owns 64 c-values ----------
    const int cbase = wid * 64;
    for (int hl = 0; hl < HT; ++hl) {
        const float4 w4 = *(const float4*)(wts + hl * M_DIM + sub * 4);
        const float* __restrict__ vbase = v + (slice0 + hl) * (long)(C_DIM * M_DIM);
        #pragma unroll
        for (int j = 0; j < 16; ++j) {
            const int c = cbase + j * 4 + grp;
            const float4 v4 = __ldcs((const float4*)(vbase + c * M_DIM + sub * 4));
            float p = v4.x * w4.x + v4.y * w4.y + v4.z * w4.z + v4.w * w4.w;
            p += __shfl_xor_sync(0xffffffffu, p, 4);
            p += __shfl_xor_sync(0xffffffffu, p, 2);
            p += __shfl_xor_sync(0xffffffffu, p, 1);
            if (sub == 0) res[c * (HT + 1) + hl] = p;
        }
    }
    __syncthreads();

    // ---------- Phase 3: coalesced transposed writes: out[((b*C + c)*W + w)*H + h] ----------
    // 256*8 floats = 512 float4; 128 threads -> 4 iterations.
    #pragma unroll
    for (int it = 0; it < 4; ++it) {
        const int j  = it * 128 + tid;
        const int c2 = j >> 1;            // 0..255
        const int hb = (j & 1) << 2;      // 0, 4
        const float* r = &res[c2 * (HT + 1) + hb];
        const float4 o4 = make_float4(r[0], r[1], r[2], r[3]);
        const long oidx = (((long)b * C_DIM + c2) * W_DIM + w) * H_DIM + (h0 + hb);
        *(float4*)(out + oidx) = o4;
    }
}

extern "C" void kernel_launch(void* const* d_in, const int* in_sizes, int n_in,
                              void* d_out, int out_size)
{
    // Resolve inputs by element count: q=16,777,216; v=134,217,728; k=524,288
    const float* q = nullptr;
    const float* v = nullptr;
    const float* k = nullptr;
    for (int i = 0; i < n_in; ++i) {
        if (in_sizes[i] == 16777216)       q = (const float*)d_in[i];
        else if (in_sizes[i] == 134217728) v = (const float*)d_in[i];
        else if (in_sizes[i] == 524288)    k = (const float*)d_in[i];
    }
    float* out = (float*)d_out;

    dim3 grid(H_DIM / HT, W_DIM, 4);   // (8, 64, 4) = 2048 CTAs
    sdpa_kernel<<<grid, 128>>>(q, v, k, out);
}

// round 5
// speedup vs baseline: 1.0423x; 1.0423x over previous
#include <cuda_runtime.h>

// ScaledDotProductAttention: B=4, W=64, H=64, C=256, M=32, D=32, T=8
// out[b,c,w,h] = sum_m v[b,w,h,c,m] * softmax_m( (q[b,w,h,m,:] . k[b,w,h,:]) / T )
//
// Pure HBM-streaming kernel (594 MB moved once).
// R2: fully coalesced 512B warp loads + shfl reductions.
// R3: 128-thread CTAs, HT=16, 1024 CTAs, single wave (90.6 us, DRAM 85.8%).
// R4 (reverted): HT=8/occ10 cut per-warp MLP and added a wave tail -> regressed.
// R5: occ bound 8->7 (reg budget 64->73 for deeper per-warp MLP, still single
//     wave: 7*148=1036 >= 1024), streaming stores (__stcs) for the output,
//     __ldcs on q. Everything else identical to R3.

#define C_DIM 256
#define M_DIM 32
#define D_DIM 32
#define W_DIM 64
#define H_DIM 64
#define HT 16          // h-tile per CTA

__global__ __launch_bounds__(128, 7)
void sdpa_kernel(const float* __restrict__ q,
                 const float* __restrict__ v,
                 const float* __restrict__ k,
                 float* __restrict__ out)
{
    __shared__ float wts[HT * M_DIM];        // [h_local][m] softmax weights, 2 KB
    __shared__ float res[C_DIM * (HT + 1)];  // [c][h_local], +1 pad, 17.4 KB

    const int hq = blockIdx.x;               // 0..3  (h-tile index)
    const int w  = blockIdx.y;               // 0..63
    const int b  = blockIdx.z;               // 0..3
    const int h0 = hq * HT;

    const int tid  = threadIdx.x;
    const int lane = tid & 31;
    const int wid  = tid >> 5;               // 0..3
    const int sub  = lane & 7;               // position within 8-lane group
    const int grp  = lane >> 3;              // which of 4 groups

    const long slice0 = ((long)(b * W_DIM + w) * H_DIM + h0);

    // ---------- Phase 1: softmax weights; warp wid owns slices wid*4 .. wid*4+3 ----------
    #pragma unroll
    for (int i = 0; i < 4; ++i) {
        const int  hl = wid * 4 + i;
        const long sl = slice0 + hl;

        const float4 k4 = *(const float4*)(k + sl * D_DIM + sub * 4);

        #pragma unroll
        for (int j = 0; j < 8; ++j) {
            const int m = j * 4 + grp;
            const float4 q4 = __ldcs((const float4*)(q + (sl * M_DIM + m) * D_DIM + sub * 4));
            float p = q4.x * k4.x + q4.y * k4.y + q4.z * k4.z + q4.w * k4.w;
            p += __shfl_xor_sync(0xffffffffu, p, 4);
            p += __shfl_xor_sync(0xffffffffu, p, 2);
            p += __shfl_xor_sync(0xffffffffu, p, 1);
            if (sub == 0) wts[hl * M_DIM + m] = p;   // raw logit
        }
        __syncwarp();

        const float logit = wts[hl * M_DIM + lane] * 0.125f;  // 1/TEMPERATURE
        float mx = logit;
        #pragma unroll
        for (int o = 16; o; o >>= 1) mx = fmaxf(mx, __shfl_xor_sync(0xffffffffu, mx, o));
        const float e = __expf(logit - mx);
        float s = e;
        #pragma unroll
        for (int o = 16; o; o >>= 1) s += __shfl_xor_sync(0xffffffffu, s, o);
        wts[hl * M_DIM + lane] = e / s;
    }
    __syncthreads();

    // ---------- Phase 2: stream v, fully coalesced; warp owns 64 c-values ----------
    const int cbase = wid * 64;
    for (int hl = 0; hl < HT; ++hl) {
        const float4 w4 = *(const float4*)(wts + hl * M_DIM + sub * 4);
        const float* __restrict__ vbase = v + (slice0 + hl) * (long)(C_DIM * M_DIM);
        #pragma unroll
        for (int j = 0; j < 16; ++j) {
            const int c = cbase + j * 4 + grp;
            const float4 v4 = __ldcs((const float4*)(vbase + c * M_DIM + sub * 4));
            float p = v4.x * w4.x + v4.y * w4.y + v4.z * w4.z + v4.w * w4.w;
            p += __shfl_xor_sync(0xffffffffu, p, 4);
            p += __shfl_xor_sync(0xffffffffu, p, 2);
            p += __shfl_xor_sync(0xffffffffu, p, 1);
            if (sub == 0) res[c * (HT + 1) + hl] = p;
        }
    }
    __syncthreads();

    // ---------- Phase 3: coalesced transposed writes: out[((b*C + c)*W + w)*H + h] ----------
    // 256*16 floats = 1024 float4; 128 threads -> 8 iterations. Streaming stores.
    #pragma unroll
    for (int it = 0; it < 8; ++it) {
        const int j  = it * 128 + tid;
        const int c2 = j >> 2;            // 0..255
        const int hb = (j & 3) << 2;      // 0,4,8,12
        const float* r = &res[c2 * (HT + 1) + hb];
        const float4 o4 = make_float4(r[0], r[1], r[2], r[3]);
        const long oidx = (((long)b * C_DIM + c2) * W_DIM + w) * H_DIM + (h0 + hb);
        __stcs((float4*)(out + oidx), o4);
    }
}

extern "C" void kernel_launch(void* const* d_in, const int* in_sizes, int n_in,
                              void* d_out, int out_size)
{
    // Resolve inputs by element count: q=16,777,216; v=134,217,728; k=524,288
    const float* q = nullptr;
    const float* v = nullptr;
    const float* k = nullptr;
    for (int i = 0; i < n_in; ++i) {
        if (in_sizes[i] == 16777216)       q = (const float*)d_in[i];
        else if (in_sizes[i] == 134217728) v = (const float*)d_in[i];
        else if (in_sizes[i] == 524288)    k = (const float*)d_in[i];
    }
    float* out = (float*)d_out;

    dim3 grid(H_DIM / HT, W_DIM, 4);   // (4, 64, 4) = 1024 CTAs
    sdpa_kernel<<<grid, 128>>>(q, v, k, out);
}

// round 6
// speedup vs baseline: 1.1126x; 1.0674x over previous
#include <cuda_runtime.h>

// ScaledDotProductAttention: B=4, W=64, H=64, C=256, M=32, D=32, T=8
// out[b,c,w,h] = sum_m v[b,w,h,c,m] * softmax_m( (q[b,w,h,m,:] . k[b,w,h,:]) / T )
//
// Pure HBM-streaming kernel (594 MB moved once).
// R2: fully coalesced 512B warp loads + shfl reductions.
// R3: 128-thread CTAs, HT=16, 1024 CTAs, occ 8, single wave (90.6 us, DRAM 85.8%).
// R4 (reverted): HT=8/occ10 cut per-warp MLP, added wave tail -> 100.8 us.
// R5 (reverted): occ 7 (regs 72) neutral-to-worse -> MLP not binding at occ 8.
// R6: exactly R3 + __stcs on the output stores (evict-first; output is
//     write-once/never-read, keep it out of L2's LRU).

#define C_DIM 256
#define M_DIM 32
#define D_DIM 32
#define W_DIM 64
#define H_DIM 64
#define HT 16          // h-tile per CTA

__global__ __launch_bounds__(128, 8)
void sdpa_kernel(const float* __restrict__ q,
                 const float* __restrict__ v,
                 const float* __restrict__ k,
                 float* __restrict__ out)
{
    __shared__ float wts[HT * M_DIM];        // [h_local][m] softmax weights, 2 KB
    __shared__ float res[C_DIM * (HT + 1)];  // [c][h_local], +1 pad, 17.4 KB

    const int hq = blockIdx.x;               // 0..3  (h-tile index)
    const int w  = blockIdx.y;               // 0..63
    const int b  = blockIdx.z;               // 0..3
    const int h0 = hq * HT;

    const int tid  = threadIdx.x;
    const int lane = tid & 31;
    const int wid  = tid >> 5;               // 0..3
    const int sub  = lane & 7;               // position within 8-lane group
    const int grp  = lane >> 3;              // which of 4 groups

    const long slice0 = ((long)(b * W_DIM + w) * H_DIM + h0);

    // ---------- Phase 1: softmax weights; warp wid owns slices wid*4 .. wid*4+3 ----------
    #pragma unroll
    for (int i = 0; i < 4; ++i) {
        const int  hl = wid * 4 + i;
        const long sl = slice0 + hl;

        const float4 k4 = *(const float4*)(k + sl * D_DIM + sub * 4);

        #pragma unroll
        for (int j = 0; j < 8; ++j) {
            const int m = j * 4 + grp;
            const float4 q4 = *(const float4*)(q + (sl * M_DIM + m) * D_DIM + sub * 4);
            float p = q4.x * k4.x + q4.y * k4.y + q4.z * k4.z + q4.w * k4.w;
            p += __shfl_xor_sync(0xffffffffu, p, 4);
            p += __shfl_xor_sync(0xffffffffu, p, 2);
            p += __shfl_xor_sync(0xffffffffu, p, 1);
            if (sub == 0) wts[hl * M_DIM + m] = p;   // raw logit
        }
        __syncwarp();

        const float logit = wts[hl * M_DIM + lane] * 0.125f;  // 1/TEMPERATURE
        float mx = logit;
        #pragma unroll
        for (int o = 16; o; o >>= 1) mx = fmaxf(mx, __shfl_xor_sync(0xffffffffu, mx, o));
        const float e = __expf(logit - mx);
        float s = e;
        #pragma unroll
        for (int o = 16; o; o >>= 1) s += __shfl_xor_sync(0xffffffffu, s, o);
        wts[hl * M_DIM + lane] = e / s;
    }
    __syncthreads();

    // ---------- Phase 2: stream v, fully coalesced; warp owns 64 c-values ----------
    const int cbase = wid * 64;
    for (int hl = 0; hl < HT; ++hl) {
        const float4 w4 = *(const float4*)(wts + hl * M_DIM + sub * 4);
        const float* __restrict__ vbase = v + (slice0 + hl) * (long)(C_DIM * M_DIM);
        #pragma unroll
        for (int j = 0; j < 16; ++j) {
            const int c = cbase + j * 4 + grp;
            const float4 v4 = __ldcs((const float4*)(vbase + c * M_DIM + sub * 4));
            float p = v4.x * w4.x + v4.y * w4.y + v4.z * w4.z + v4.w * w4.w;
            p += __shfl_xor_sync(0xffffffffu, p, 4);
            p += __shfl_xor_sync(0xffffffffu, p, 2);
            p += __shfl_xor_sync(0xffffffffu, p, 1);
            if (sub == 0) res[c * (HT + 1) + hl] = p;
        }
    }
    __syncthreads();

    // ---------- Phase 3: coalesced transposed writes: out[((b*C + c)*W + w)*H + h] ----------
    // 256*16 floats = 1024 float4; 128 threads -> 8 iterations. Streaming stores.
    #pragma unroll
    for (int it = 0; it < 8; ++it) {
        const int j  = it * 128 + tid;
        const int c2 = j >> 2;            // 0..255
        const int hb = (j & 3) << 2;      // 0,4,8,12
        const float* r = &res[c2 * (HT + 1) + hb];
        const float4 o4 = make_float4(r[0], r[1], r[2], r[3]);
        const long oidx = (((long)b * C_DIM + c2) * W_DIM + w) * H_DIM + (h0 + hb);
        __stcs((float4*)(out + oidx), o4);
    }
}

extern "C" void kernel_launch(void* const* d_in, const int* in_sizes, int n_in,
                              void* d_out, int out_size)
{
    // Resolve inputs by element count: q=16,777,216; v=134,217,728; k=524,288
    const float* q = nullptr;
    const float* v = nullptr;
    const float* k = nullptr;
    for (int i = 0; i < n_in; ++i) {
        if (in_sizes[i] == 16777216)       q = (const float*)d_in[i];
        else if (in_sizes[i] == 134217728) v = (const float*)d_in[i];
        else if (in_sizes[i] == 524288)    k = (const float*)d_in[i];
    }
    float* out = (float*)d_out;

    dim3 grid(H_DIM / HT, W_DIM, 4);   // (4, 64, 4) = 1024 CTAs
    sdpa_kernel<<<grid, 128>>>(q, v, k, out);
}